// round 1
// baseline (speedup 1.0000x reference)
#include <cuda_runtime.h>
#include <cuda_bf16.h>

#define SS   2048
#define BB   64
#define HH   8
#define KK   12
#define NPOS 11

// Scratch (no allocations allowed)
__device__ __align__(16) unsigned short d_aq[SS * HH];
__device__ __align__(16) unsigned short d_ak[SS * HH];
__device__ __align__(16) unsigned short d_ap[SS * HH];
__device__ unsigned int   d_bits[HH * 128];     // head_table packed: bit a of head h
__device__ unsigned short d_addrv[SS * BB];     // value-table addresses per (s,b)
__device__ int d_best[SS];
__device__ int d_maxv[SS];

// ---------------------------------------------------------------------------
// Kernel 1: precompute addr tables + packed bitsets
// ---------------------------------------------------------------------------
__global__ void prep_kernel(const int* __restrict__ tokens,
                            const int* __restrict__ conn_heads,
                            const float* __restrict__ head_table,
                            const int* __restrict__ conn_v) {
    int idx = blockIdx.x * blockDim.x + threadIdx.x;
    if (idx < SS * BB) {
        // addr_v[s][b] = sum_j tokens[s, conn_v[b,j]] * 2^(K-1-j)
        int s = idx >> 6, b = idx & 63;
        int a = 0;
#pragma unroll
        for (int j = 0; j < KK; j++) {
            int c = conn_v[b * KK + j];
            a += tokens[s * BB + c] << (KK - 1 - j);
        }
        d_addrv[idx] = (unsigned short)a;
    } else if (idx < SS * BB + SS * HH) {
        // aq/ak/ap per (s, h). Bit groups are disjoint by construction.
        int t = idx - SS * BB;
        int s = t >> 3, h = t & 7;
        int aq = 0, ak = 0, ap = 0;
#pragma unroll
        for (int j = 0; j < KK; j++) {
            int c  = conn_heads[h * KK + j];
            int p2 = 1 << (KK - 1 - j);
            if (c < BB)            aq += tokens[s * BB + c] * p2;
            else if (c < 2 * BB)   ak += tokens[s * BB + (c - BB)] * p2;
            else                   ap += ((s >> (NPOS - 1 - (c - 2 * BB))) & 1) * p2;
        }
        d_aq[s * HH + h] = (unsigned short)aq;
        d_ak[s * HH + h] = (unsigned short)ak;
        d_ap[s * HH + h] = (unsigned short)ap;
    } else if (idx < SS * BB + SS * HH + HH * 128) {
        // pack head_table (exact 0.0/1.0 floats) into bits
        int t = idx - SS * BB - SS * HH;          // t = h*128 + word
        const float* p = head_table + t * 32;
        unsigned int bits = 0;
#pragma unroll
        for (int e = 0; e < 32; e++)
            bits |= (p[e] != 0.0f ? 1u : 0u) << e;
        d_bits[t] = bits;
    }
}

// ---------------------------------------------------------------------------
// Kernel 2: per-row causal scan: max + first argmax of votes, early-exit at 8
// One warp per row; 8 warps (8 rows) per block; bitset in shared (4 KB).
// ---------------------------------------------------------------------------
__global__ void scan_kernel() {
    __shared__ unsigned int sbits[HH * 128];
    int tid = threadIdx.x;
    for (int i = tid; i < HH * 128; i += blockDim.x) sbits[i] = d_bits[i];
    __syncthreads();

    int warp = tid >> 5, lane = tid & 31;
    int row = blockIdx.x + warp * gridDim.x;   // strided mapping for balance
    if (row >= SS) return;

    int aq[HH];
#pragma unroll
    for (int h = 0; h < HH; h++) aq[h] = d_aq[row * HH + h];

    const uint4* ak4 = (const uint4*)d_ak;
    const uint4* ap4 = (const uint4*)d_ap;

    int best_max = -1, best_j = 0;
    int ntiles = (row >> 5) + 1;
    for (int t = 0; t < ntiles; t++) {
        int j = (t << 5) + lane;
        int v = -1;
        if (j <= row) {
            uint4 kk = ak4[j];
            uint4 pp = ap4[row - j];
            int k0 = kk.x & 0xffff, k1 = kk.x >> 16;
            int k2 = kk.y & 0xffff, k3 = kk.y >> 16;
            int k4 = kk.z & 0xffff, k5 = kk.z >> 16;
            int k6 = kk.w & 0xffff, k7 = kk.w >> 16;
            int p0 = pp.x & 0xffff, p1 = pp.x >> 16;
            int p2 = pp.y & 0xffff, p3 = pp.y >> 16;
            int p4 = pp.z & 0xffff, p5 = pp.z >> 16;
            int p6 = pp.w & 0xffff, p7 = pp.w >> 16;
            int a0 = aq[0] + k0 + p0;
            int a1 = aq[1] + k1 + p1;
            int a2 = aq[2] + k2 + p2;
            int a3 = aq[3] + k3 + p3;
            int a4 = aq[4] + k4 + p4;
            int a5 = aq[5] + k5 + p5;
            int a6 = aq[6] + k6 + p6;
            int a7 = aq[7] + k7 + p7;
            v  = (int)((sbits[(0 << 7) + (a0 >> 5)] >> (a0 & 31)) & 1u);
            v += (int)((sbits[(1 << 7) + (a1 >> 5)] >> (a1 & 31)) & 1u);
            v += (int)((sbits[(2 << 7) + (a2 >> 5)] >> (a2 & 31)) & 1u);
            v += (int)((sbits[(3 << 7) + (a3 >> 5)] >> (a3 & 31)) & 1u);
            v += (int)((sbits[(4 << 7) + (a4 >> 5)] >> (a4 & 31)) & 1u);
            v += (int)((sbits[(5 << 7) + (a5 >> 5)] >> (a5 & 31)) & 1u);
            v += (int)((sbits[(6 << 7) + (a6 >> 5)] >> (a6 & 31)) & 1u);
            v += (int)((sbits[(7 << 7) + (a7 >> 5)] >> (a7 & 31)) & 1u);
        }
        // warp-wide max (lane j = t*32 is always valid, so m >= 0)
        int m = v;
#pragma unroll
        for (int o = 16; o; o >>= 1) m = max(m, __shfl_xor_sync(0xffffffffu, m, o));
        unsigned mask = __ballot_sync(0xffffffffu, v == m);
        int fj = (t << 5) + (__ffs(mask) - 1);
        if (m == HH) { best_max = m; best_j = fj; break; }  // 8 = ceiling -> first 8 is the argmax
        if (m > best_max) { best_max = m; best_j = fj; }    // strict: keep earliest index
    }
    if (lane == 0) { d_best[row] = best_j; d_maxv[row] = best_max; }
}

// ---------------------------------------------------------------------------
// Kernel 3: gather output
// ---------------------------------------------------------------------------
__global__ void out_kernel(const float* __restrict__ table_v,
                           float* __restrict__ out) {
    int idx = blockIdx.x * blockDim.x + threadIdx.x;
    if (idx >= SS * BB) return;
    int i = idx >> 6, b = idx & 63;
    float r = 0.0f;
    if (d_maxv[i] > 0) {
        int s = d_best[i];
        r = table_v[b * 4096 + (int)d_addrv[s * BB + b]];
    }
    out[idx] = r;
}

// ---------------------------------------------------------------------------
extern "C" void kernel_launch(void* const* d_in, const int* in_sizes, int n_in,
                              void* d_out, int out_size) {
    const int*   tokens     = (const int*)d_in[0];
    const int*   conn_heads = (const int*)d_in[1];
    const float* head_table = (const float*)d_in[2];
    const int*   conn_v     = (const int*)d_in[3];
    const float* table_v    = (const float*)d_in[4];
    float*       out        = (float*)d_out;

    int prep_total = SS * BB + SS * HH + HH * 128;
    prep_kernel<<<(prep_total + 255) / 256, 256>>>(tokens, conn_heads, head_table, conn_v);
    scan_kernel<<<256, 256>>>();
    out_kernel<<<(SS * BB + 255) / 256, 256>>>(table_v, out);
}

// round 2
// speedup vs baseline: 1.3596x; 1.3596x over previous
#include <cuda_runtime.h>
#include <cuda_bf16.h>

#define SS   2048
#define BB   64
#define HH   8
#define KK   12
#define NPOS 11

// Scratch (no allocations allowed)
__device__ unsigned int   d_bits[HH * 128];     // head_table packed bitsets
__device__ unsigned short d_addrv[SS * BB];     // value-table addresses per (s,b)
__device__ __align__(16) unsigned short d_aq[SS * HH];
__device__ __align__(16) unsigned short d_ak[SS * HH];
__device__ __align__(16) unsigned short d_ap[SS * HH];

// ---------------------------------------------------------------------------
// Kernel 1: precompute everything. Grid = 512 blocks x 256 threads.
//   - blocks 0..127 additionally ballot-pack head_table into d_bits
//   - each block packs its 4 token rows into uint64 via ballot, then computes
//     addr_v (256 threads) and aq/ak/ap (32 threads) with pure ALU.
// ---------------------------------------------------------------------------
__global__ void prep_kernel(const int* __restrict__ tokens,
                            const int* __restrict__ conn_heads,
                            const float* __restrict__ head_table,
                            const int* __restrict__ conn_v) {
    __shared__ int sconn_v[BB * KK];
    __shared__ int sconn_h[HH * KK];
    __shared__ unsigned long long stok[4];

    int tid  = threadIdx.x;
    int warp = tid >> 5, lane = tid & 31;

    // Pack head_table bits: 1024 words total, blocks 0..127 x 8 warps.
    if (blockIdx.x < 128) {
        int t = blockIdx.x * 8 + warp;                      // word index 0..1023
        unsigned m = __ballot_sync(0xffffffffu, head_table[t * 32 + lane] != 0.0f);
        if (lane == 0) d_bits[t] = m;
    }

    int s0 = blockIdx.x * 4;
    // Pack 4 token rows (binary) into uint64 each: warps 0..3.
    if (warp < 4) {
        const int* trow = tokens + (s0 + warp) * BB;
        unsigned lo = __ballot_sync(0xffffffffu, trow[lane] != 0);
        unsigned hi = __ballot_sync(0xffffffffu, trow[lane + 32] != 0);
        if (lane == 0)
            stok[warp] = (unsigned long long)lo | ((unsigned long long)hi << 32);
    }
    // Stage conn tables.
    for (int i = tid; i < BB * KK; i += 256) sconn_v[i] = conn_v[i];
    if (tid < HH * KK) sconn_h[tid] = conn_heads[tid];
    __syncthreads();

    // addr_v for (4 rows x 64 b) — one per thread, pure bit extracts.
    {
        int sl = tid >> 6, b = tid & 63;
        unsigned long long tok = stok[sl];
        int a = 0;
#pragma unroll
        for (int j = 0; j < KK; j++) {
            int c = sconn_v[b * KK + j];
            a |= (int)((tok >> c) & 1ull) << (KK - 1 - j);
        }
        d_addrv[(s0 + sl) * BB + b] = (unsigned short)a;
    }

    // aq/ak/ap for (4 rows x 8 heads) — threads 0..31.
    if (tid < 32) {
        int sl = tid >> 3, h = tid & 7;
        int s = s0 + sl;
        unsigned long long tok = stok[sl];
        int aq = 0, ak = 0, ap = 0;
#pragma unroll
        for (int j = 0; j < KK; j++) {
            int c  = sconn_h[h * KK + j];
            int p2 = 1 << (KK - 1 - j);
            if (c < BB)            aq |= (int)((tok >> c) & 1ull) * p2;
            else if (c < 2 * BB)   ak |= (int)((tok >> (c - BB)) & 1ull) * p2;
            else                   ap |= ((s >> (NPOS - 1 - (c - 2 * BB))) & 1) * p2;
        }
        d_aq[s * HH + h] = (unsigned short)aq;
        d_ak[s * HH + h] = (unsigned short)ak;
        d_ap[s * HH + h] = (unsigned short)ap;
    }
}

// ---------------------------------------------------------------------------
// Kernel 2: per-row causal scan (max + first argmax, early exit at votes==8)
// fused with the output gather. Warp per row; 512 blocks x 128 threads.
// ---------------------------------------------------------------------------
__global__ void scan_kernel(const float* __restrict__ table_v,
                            float* __restrict__ out) {
    __shared__ unsigned int sbits[HH * 128];
    int tid = threadIdx.x;
    for (int i = tid; i < HH * 128; i += 128) sbits[i] = d_bits[i];
    __syncthreads();

    int warp = tid >> 5, lane = tid & 31;
    int row = blockIdx.x + warp * gridDim.x;   // strided mapping for balance
    if (row >= SS) return;

    int aq[HH];
#pragma unroll
    for (int h = 0; h < HH; h++) aq[h] = d_aq[row * HH + h];

    const uint4* ak4 = (const uint4*)d_ak;
    const uint4* ap4 = (const uint4*)d_ap;

    int best_max = -1, best_j = 0;
    int ntiles = (row >> 5) + 1;
    for (int t = 0; t < ntiles; t++) {
        int j = (t << 5) + lane;
        int v = -1;
        if (j <= row) {
            uint4 kk = ak4[j];
            uint4 pp = ap4[row - j];
            int a0 = aq[0] + (kk.x & 0xffff) + (pp.x & 0xffff);
            int a1 = aq[1] + (kk.x >> 16)    + (pp.x >> 16);
            int a2 = aq[2] + (kk.y & 0xffff) + (pp.y & 0xffff);
            int a3 = aq[3] + (kk.y >> 16)    + (pp.y >> 16);
            int a4 = aq[4] + (kk.z & 0xffff) + (pp.z & 0xffff);
            int a5 = aq[5] + (kk.z >> 16)    + (pp.z >> 16);
            int a6 = aq[6] + (kk.w & 0xffff) + (pp.w & 0xffff);
            int a7 = aq[7] + (kk.w >> 16)    + (pp.w >> 16);
            v  = (int)((sbits[(0 << 7) + (a0 >> 5)] >> (a0 & 31)) & 1u);
            v += (int)((sbits[(1 << 7) + (a1 >> 5)] >> (a1 & 31)) & 1u);
            v += (int)((sbits[(2 << 7) + (a2 >> 5)] >> (a2 & 31)) & 1u);
            v += (int)((sbits[(3 << 7) + (a3 >> 5)] >> (a3 & 31)) & 1u);
            v += (int)((sbits[(4 << 7) + (a4 >> 5)] >> (a4 & 31)) & 1u);
            v += (int)((sbits[(5 << 7) + (a5 >> 5)] >> (a5 & 31)) & 1u);
            v += (int)((sbits[(6 << 7) + (a6 >> 5)] >> (a6 & 31)) & 1u);
            v += (int)((sbits[(7 << 7) + (a7 >> 5)] >> (a7 & 31)) & 1u);
        }
        int m = __reduce_max_sync(0xffffffffu, v);       // single REDUX
        if (m > best_max) {                              // ballot only on improvement
            unsigned mask = __ballot_sync(0xffffffffu, v == m);
            best_j = (t << 5) + (__ffs(mask) - 1);
            best_max = m;
            if (m == HH) break;      // 8 = ceiling -> first 8 is the argmax
        }
    }

    // Fused output: all lanes hold warp-uniform (best_max, best_j).
    float* orow = out + row * BB;
    if (best_max > 0) {
        int a0 = d_addrv[best_j * BB + lane];
        int a1 = d_addrv[best_j * BB + lane + 32];
        orow[lane]      = table_v[lane * 4096 + a0];
        orow[lane + 32] = table_v[(lane + 32) * 4096 + a1];
    } else {
        orow[lane]      = 0.0f;
        orow[lane + 32] = 0.0f;
    }
}

// ---------------------------------------------------------------------------
extern "C" void kernel_launch(void* const* d_in, const int* in_sizes, int n_in,
                              void* d_out, int out_size) {
    const int*   tokens     = (const int*)d_in[0];
    const int*   conn_heads = (const int*)d_in[1];
    const float* head_table = (const float*)d_in[2];
    const int*   conn_v     = (const int*)d_in[3];
    const float* table_v    = (const float*)d_in[4];
    float*       out        = (float*)d_out;

    prep_kernel<<<512, 256>>>(tokens, conn_heads, head_table, conn_v);
    scan_kernel<<<512, 128>>>(table_v, out);
}

// round 3
// speedup vs baseline: 2.1233x; 1.5616x over previous
#include <cuda_runtime.h>
#include <cuda_bf16.h>

#define SS   2048
#define BB   64
#define HH   8
#define KK   12
#define NPOS 11

// Scratch (no allocations allowed)
__device__ unsigned int   d_bits[HH * 128];     // head_table packed bitsets
__device__ unsigned short d_addrv[SS * BB];     // value-table addresses per (s,b)
__device__ __align__(16) unsigned short d_aq[SS * HH];
__device__ __align__(16) unsigned short d_ak[SS * HH];
__device__ __align__(16) unsigned short d_ap[SS * HH];

// ---------------------------------------------------------------------------
// Kernel 1: precompute everything. Grid = 512 blocks x 256 threads.
// ---------------------------------------------------------------------------
__global__ void prep_kernel(const int* __restrict__ tokens,
                            const int* __restrict__ conn_heads,
                            const float* __restrict__ head_table,
                            const int* __restrict__ conn_v) {
    __shared__ int sconn_v[BB * KK];
    __shared__ int sconn_h[HH * KK];
    __shared__ unsigned long long stok[4];

    int tid  = threadIdx.x;
    int warp = tid >> 5, lane = tid & 31;

    // Pack head_table bits: 1024 words total, blocks 0..127 x 8 warps.
    if (blockIdx.x < 128) {
        int t = blockIdx.x * 8 + warp;
        unsigned m = __ballot_sync(0xffffffffu, head_table[t * 32 + lane] != 0.0f);
        if (lane == 0) d_bits[t] = m;
    }

    int s0 = blockIdx.x * 4;
    // Pack 4 token rows (binary) into uint64 each: warps 0..3.
    if (warp < 4) {
        const int* trow = tokens + (s0 + warp) * BB;
        unsigned lo = __ballot_sync(0xffffffffu, trow[lane] != 0);
        unsigned hi = __ballot_sync(0xffffffffu, trow[lane + 32] != 0);
        if (lane == 0)
            stok[warp] = (unsigned long long)lo | ((unsigned long long)hi << 32);
    }
    for (int i = tid; i < BB * KK; i += 256) sconn_v[i] = conn_v[i];
    if (tid < HH * KK) sconn_h[tid] = conn_heads[tid];
    __syncthreads();

    // addr_v for (4 rows x 64 b) — one per thread, pure bit extracts.
    {
        int sl = tid >> 6, b = tid & 63;
        unsigned long long tok = stok[sl];
        int a = 0;
#pragma unroll
        for (int j = 0; j < KK; j++) {
            int c = sconn_v[b * KK + j];
            a |= (int)((tok >> c) & 1ull) << (KK - 1 - j);
        }
        d_addrv[(s0 + sl) * BB + b] = (unsigned short)a;
    }

    // aq/ak/ap for (4 rows x 8 heads) — threads 0..31.
    if (tid < 32) {
        int sl = tid >> 3, h = tid & 7;
        int s = s0 + sl;
        unsigned long long tok = stok[sl];
        int aq = 0, ak = 0, ap = 0;
#pragma unroll
        for (int j = 0; j < KK; j++) {
            int c  = sconn_h[h * KK + j];
            int p2 = 1 << (KK - 1 - j);
            if (c < BB)            aq |= (int)((tok >> c) & 1ull) * p2;
            else if (c < 2 * BB)   ak |= (int)((tok >> (c - BB)) & 1ull) * p2;
            else                   ap |= ((s >> (NPOS - 1 - (c - 2 * BB))) & 1) * p2;
        }
        d_aq[s * HH + h] = (unsigned short)aq;
        d_ak[s * HH + h] = (unsigned short)ak;
        d_ap[s * HH + h] = (unsigned short)ap;
    }
}

// ---------------------------------------------------------------------------
// Kernel 2: block-per-row causal scan. 2048 blocks x 128 threads.
// 128 columns per iteration; early-exit via __syncthreads_or when any v==8.
// No-8 path: per-thread local best, single packed-key block reduce at end.
// ---------------------------------------------------------------------------
__global__ void __launch_bounds__(128) scan_kernel(const float* __restrict__ table_v,
                                                   float* __restrict__ out) {
    __shared__ unsigned int sbits[HH * 128];
    __shared__ unsigned int wmask[4];
    __shared__ int skey[4];

    int tid  = threadIdx.x;
    int warp = tid >> 5, lane = tid & 31;
    int row  = blockIdx.x;

    for (int i = tid; i < HH * 128; i += 128) sbits[i] = d_bits[i];
    __syncthreads();

    // aq row: 8 x u16 = one uint4 broadcast load.
    uint4 qq = ((const uint4*)d_aq)[row];
    int q0 = qq.x & 0xffff, q1 = qq.x >> 16;
    int q2 = qq.y & 0xffff, q3 = qq.y >> 16;
    int q4 = qq.z & 0xffff, q5 = qq.z >> 16;
    int q6 = qq.w & 0xffff, q7 = qq.w >> 16;

    const uint4* ak4 = (const uint4*)d_ak;
    const uint4* ap4 = (const uint4*)d_ap;

    int best_v = -1, best_j = 0;
    bool found8 = false;

    for (int base = 0; base <= row; base += 128) {
        int j = base + tid;
        int v = -1;
        if (j <= row) {
            uint4 kk = ak4[j];
            uint4 pp = ap4[row - j];
            int a0 = q0 + (kk.x & 0xffff) + (pp.x & 0xffff);
            int a1 = q1 + (kk.x >> 16)    + (pp.x >> 16);
            int a2 = q2 + (kk.y & 0xffff) + (pp.y & 0xffff);
            int a3 = q3 + (kk.y >> 16)    + (pp.y >> 16);
            int a4 = q4 + (kk.z & 0xffff) + (pp.z & 0xffff);
            int a5 = q5 + (kk.z >> 16)    + (pp.z >> 16);
            int a6 = q6 + (kk.w & 0xffff) + (pp.w & 0xffff);
            int a7 = q7 + (kk.w >> 16)    + (pp.w >> 16);
            v  = (int)((sbits[(0 << 7) + (a0 >> 5)] >> (a0 & 31)) & 1u);
            v += (int)((sbits[(1 << 7) + (a1 >> 5)] >> (a1 & 31)) & 1u);
            v += (int)((sbits[(2 << 7) + (a2 >> 5)] >> (a2 & 31)) & 1u);
            v += (int)((sbits[(3 << 7) + (a3 >> 5)] >> (a3 & 31)) & 1u);
            v += (int)((sbits[(4 << 7) + (a4 >> 5)] >> (a4 & 31)) & 1u);
            v += (int)((sbits[(5 << 7) + (a5 >> 5)] >> (a5 & 31)) & 1u);
            v += (int)((sbits[(6 << 7) + (a6 >> 5)] >> (a6 & 31)) & 1u);
            v += (int)((sbits[(7 << 7) + (a7 >> 5)] >> (a7 & 31)) & 1u);
        }
        if (__syncthreads_or(v == HH)) {
            // earliest j with v==8 in this iteration = min tid with v==8
            unsigned m = __ballot_sync(0xffffffffu, v == HH);
            if (lane == 0) wmask[warp] = m;
            __syncthreads();
            int ft = -1;
#pragma unroll
            for (int w = 3; w >= 0; w--)
                if (wmask[w]) ft = w * 32 + (__ffs(wmask[w]) - 1);
            best_v = HH;
            best_j = base + ft;
            found8 = true;
            break;
        }
        if (v > best_v) { best_v = v; best_j = j; }   // ascending j per thread
    }

    if (!found8) {
        // block argmax: max v, then min j. key = (v<<11) | (2047 - j).
        int key = (best_v << 11) | (2047 - best_j);
        key = __reduce_max_sync(0xffffffffu, key);
        if (lane == 0) skey[warp] = key;
        __syncthreads();
        key = max(max(skey[0], skey[1]), max(skey[2], skey[3]));
        best_v = key >> 11;
        best_j = 2047 - (key & 2047);
    }

    // Output row (threads 0..63), block-uniform (best_v, best_j).
    if (tid < BB) {
        float r = 0.0f;
        if (best_v > 0) {
            int a = d_addrv[best_j * BB + tid];
            r = table_v[tid * 4096 + a];
        }
        out[row * BB + tid] = r;
    }
}

// ---------------------------------------------------------------------------
extern "C" void kernel_launch(void* const* d_in, const int* in_sizes, int n_in,
                              void* d_out, int out_size) {
    const int*   tokens     = (const int*)d_in[0];
    const int*   conn_heads = (const int*)d_in[1];
    const float* head_table = (const float*)d_in[2];
    const int*   conn_v     = (const int*)d_in[3];
    const float* table_v    = (const float*)d_in[4];
    float*       out        = (float*)d_out;

    prep_kernel<<<512, 256>>>(tokens, conn_heads, head_table, conn_v);
    scan_kernel<<<SS, 128>>>(table_v, out);
}

// round 4
// speedup vs baseline: 2.4078x; 1.1340x over previous
#include <cuda_runtime.h>
#include <cuda_bf16.h>

#define SS   2048
#define BB   64
#define HH   8
#define KK   12
#define NPOS 11

// Scratch (no allocations allowed)
__device__ unsigned int   d_bits[HH * 128];     // head_table packed bitsets
__device__ unsigned short d_addrv[SS * BB];     // value-table addresses per (s,b)
__device__ __align__(16) unsigned short d_aq[SS * HH];
__device__ __align__(16) unsigned short d_ak[SS * HH];
__device__ __align__(16) unsigned short d_ap[SS * HH];

// ---------------------------------------------------------------------------
// Kernel 1: precompute everything. Grid = 512 blocks x 256 threads.
// ---------------------------------------------------------------------------
__global__ void prep_kernel(const int* __restrict__ tokens,
                            const int* __restrict__ conn_heads,
                            const float* __restrict__ head_table,
                            const int* __restrict__ conn_v) {
    __shared__ int sconn_v[BB * KK];
    __shared__ int sconn_h[HH * KK];
    __shared__ unsigned long long stok[4];

    int tid  = threadIdx.x;
    int warp = tid >> 5, lane = tid & 31;

    // Pack head_table bits: 1024 words total, blocks 0..127 x 8 warps.
    if (blockIdx.x < 128) {
        int t = blockIdx.x * 8 + warp;
        unsigned m = __ballot_sync(0xffffffffu, head_table[t * 32 + lane] != 0.0f);
        if (lane == 0) d_bits[t] = m;
    }

    int s0 = blockIdx.x * 4;
    // Pack 4 token rows (binary) into uint64 each: warps 0..3.
    if (warp < 4) {
        const int* trow = tokens + (s0 + warp) * BB;
        unsigned lo = __ballot_sync(0xffffffffu, trow[lane] != 0);
        unsigned hi = __ballot_sync(0xffffffffu, trow[lane + 32] != 0);
        if (lane == 0)
            stok[warp] = (unsigned long long)lo | ((unsigned long long)hi << 32);
    }
    for (int i = tid; i < BB * KK; i += 256) sconn_v[i] = conn_v[i];
    if (tid < HH * KK) sconn_h[tid] = conn_heads[tid];
    __syncthreads();

    // addr_v for (4 rows x 64 b) — one per thread, pure bit extracts.
    {
        int sl = tid >> 6, b = tid & 63;
        unsigned long long tok = stok[sl];
        int a = 0;
#pragma unroll
        for (int j = 0; j < KK; j++) {
            int c = sconn_v[b * KK + j];
            a |= (int)((tok >> c) & 1ull) << (KK - 1 - j);
        }
        d_addrv[(s0 + sl) * BB + b] = (unsigned short)a;
    }

    // aq/ak/ap for (4 rows x 8 heads) — threads 0..31.
    if (tid < 32) {
        int sl = tid >> 3, h = tid & 7;
        int s = s0 + sl;
        unsigned long long tok = stok[sl];
        int aq = 0, ak = 0, ap = 0;
#pragma unroll
        for (int j = 0; j < KK; j++) {
            int c  = sconn_h[h * KK + j];
            int p2 = 1 << (KK - 1 - j);
            if (c < BB)            aq |= (int)((tok >> c) & 1ull) * p2;
            else if (c < 2 * BB)   ak |= (int)((tok >> (c - BB)) & 1ull) * p2;
            else                   ap |= ((s >> (NPOS - 1 - (c - 2 * BB))) & 1) * p2;
        }
        d_aq[s * HH + h] = (unsigned short)aq;
        d_ak[s * HH + h] = (unsigned short)ak;
        d_ap[s * HH + h] = (unsigned short)ap;
    }
}

// ---------------------------------------------------------------------------
// votes for one column given preloaded kk/pp and broadcast q terms
__device__ __forceinline__ int votes8(const unsigned int* sbits, uint4 kk, uint4 pp,
                                      int q0, int q1, int q2, int q3,
                                      int q4, int q5, int q6, int q7) {
    int a0 = q0 + (kk.x & 0xffff) + (pp.x & 0xffff);
    int a1 = q1 + (kk.x >> 16)    + (pp.x >> 16);
    int a2 = q2 + (kk.y & 0xffff) + (pp.y & 0xffff);
    int a3 = q3 + (kk.y >> 16)    + (pp.y >> 16);
    int a4 = q4 + (kk.z & 0xffff) + (pp.z & 0xffff);
    int a5 = q5 + (kk.z >> 16)    + (pp.z >> 16);
    int a6 = q6 + (kk.w & 0xffff) + (pp.w & 0xffff);
    int a7 = q7 + (kk.w >> 16)    + (pp.w >> 16);
    int v;
    v  = (int)((sbits[(0 << 7) + (a0 >> 5)] >> (a0 & 31)) & 1u);
    v += (int)((sbits[(1 << 7) + (a1 >> 5)] >> (a1 & 31)) & 1u);
    v += (int)((sbits[(2 << 7) + (a2 >> 5)] >> (a2 & 31)) & 1u);
    v += (int)((sbits[(3 << 7) + (a3 >> 5)] >> (a3 & 31)) & 1u);
    v += (int)((sbits[(4 << 7) + (a4 >> 5)] >> (a4 & 31)) & 1u);
    v += (int)((sbits[(5 << 7) + (a5 >> 5)] >> (a5 & 31)) & 1u);
    v += (int)((sbits[(6 << 7) + (a6 >> 5)] >> (a6 & 31)) & 1u);
    v += (int)((sbits[(7 << 7) + (a7 >> 5)] >> (a7 & 31)) & 1u);
    return v;
}

// ---------------------------------------------------------------------------
// Kernel 2: block-per-row causal scan. 2048 blocks x 128 threads.
// 256 columns per iteration (2 per thread, MLP=4 LDGs); early-exit via
// __syncthreads_or; first-argmax resolved group-1-then-group-2.
// ---------------------------------------------------------------------------
__global__ void __launch_bounds__(128) scan_kernel(const float* __restrict__ table_v,
                                                   float* __restrict__ out) {
    __shared__ unsigned int sbits[HH * 128];
    __shared__ unsigned int wm1[4], wm2[4];
    __shared__ int skey[4];

    int tid  = threadIdx.x;
    int warp = tid >> 5, lane = tid & 31;
    int row  = blockIdx.x;

    for (int i = tid; i < HH * 128; i += 128) sbits[i] = d_bits[i];
    __syncthreads();

    uint4 qq = ((const uint4*)d_aq)[row];
    int q0 = qq.x & 0xffff, q1 = qq.x >> 16;
    int q2 = qq.y & 0xffff, q3 = qq.y >> 16;
    int q4 = qq.z & 0xffff, q5 = qq.z >> 16;
    int q6 = qq.w & 0xffff, q7 = qq.w >> 16;

    const uint4* ak4 = (const uint4*)d_ak;
    const uint4* ap4 = (const uint4*)d_ap;

    int best_v = -1, best_j = 0;
    bool found8 = false;

    for (int base = 0; base <= row; base += 256) {
        int j1 = base + tid;
        int j2 = j1 + 128;
        // Issue all loads up front (up to 4 outstanding LDG.128).
        uint4 kk1, pp1, kk2, pp2;
        bool in1 = (j1 <= row), in2 = (j2 <= row);
        if (in1) { kk1 = ak4[j1]; pp1 = ap4[row - j1]; }
        if (in2) { kk2 = ak4[j2]; pp2 = ap4[row - j2]; }

        int v1 = -1, v2 = -1;
        if (in1) v1 = votes8(sbits, kk1, pp1, q0, q1, q2, q3, q4, q5, q6, q7);
        if (in2) v2 = votes8(sbits, kk2, pp2, q0, q1, q2, q3, q4, q5, q6, q7);

        if (__syncthreads_or((v1 == HH) | (v2 == HH))) {
            unsigned m1 = __ballot_sync(0xffffffffu, v1 == HH);
            unsigned m2 = __ballot_sync(0xffffffffu, v2 == HH);
            if (lane == 0) { wm1[warp] = m1; wm2[warp] = m2; }
            __syncthreads();
            int ft = -1;
#pragma unroll
            for (int w = 3; w >= 0; w--)
                if (wm1[w]) ft = w * 32 + (__ffs(wm1[w]) - 1);
            if (ft >= 0) best_j = base + ft;
            else {
#pragma unroll
                for (int w = 3; w >= 0; w--)
                    if (wm2[w]) ft = w * 32 + (__ffs(wm2[w]) - 1);
                best_j = base + 128 + ft;
            }
            best_v = HH;
            found8 = true;
            break;
        }
        // ascending-j updates (j1 < j2), strict > keeps earliest index
        if (v1 > best_v) { best_v = v1; best_j = j1; }
        if (v2 > best_v) { best_v = v2; best_j = j2; }
    }

    if (!found8) {
        // block argmax: max v, then min j. key = (v<<11) | (2047 - j).
        int key = (best_v << 11) | (2047 - best_j);
        key = __reduce_max_sync(0xffffffffu, key);
        if (lane == 0) skey[warp] = key;
        __syncthreads();
        key = max(max(skey[0], skey[1]), max(skey[2], skey[3]));
        best_v = key >> 11;
        best_j = 2047 - (key & 2047);
    }

    // Output row (threads 0..63), block-uniform (best_v, best_j).
    if (tid < BB) {
        float r = 0.0f;
        if (best_v > 0) {
            int a = d_addrv[best_j * BB + tid];
            r = table_v[tid * 4096 + a];
        }
        out[row * BB + tid] = r;
    }
}

// ---------------------------------------------------------------------------
extern "C" void kernel_launch(void* const* d_in, const int* in_sizes, int n_in,
                              void* d_out, int out_size) {
    const int*   tokens     = (const int*)d_in[0];
    const int*   conn_heads = (const int*)d_in[1];
    const float* head_table = (const float*)d_in[2];
    const int*   conn_v     = (const int*)d_in[3];
    const float* table_v    = (const float*)d_in[4];
    float*       out        = (float*)d_out;

    prep_kernel<<<512, 256>>>(tokens, conn_heads, head_table, conn_v);
    scan_kernel<<<SS, 128>>>(table_v, out);
}